// round 14
// baseline (speedup 1.0000x reference)
#include <cuda_runtime.h>
#include <cuda_bf16.h>
#include <math.h>
#include <cstdint>

// InfoNCE loss. B=16384, D=256, T=0.07. int8 IMMA path (compute_103-safe).
// Per-row symmetric int8 quantization of the normalized embeddings; s32 MMA
// accumulation is exact; dequant (sq[row]*sd[col], log2e/T folded into sq)
// happens in the epilogue before ex2. Fixed shift M2 = log2e/T >= any logit
// -> stable LSE, no atomics, deterministic. sim (1 GB) never materialized.
// Persistent row-tile CTAs (128), 512 threads, 3-stage cp.async B pipeline.

#define B_N 16384
#define D_K 256
#define NT  128
#define LOG2E 1.4426950408889634f
#define LN2   0.6931471805599453f
#define M2_SHIFT (14.285714285714286f * LOG2E)   // (1/T) * log2(e)

static __device__ uint8_t g_q8[B_N * D_K];   // int8 quantized q-hat
static __device__ uint8_t g_d8[B_N * D_K];   // int8 quantized d-hat
static __device__ float g_sq[B_N];           // q row scale * log2e/T
static __device__ float g_sd[B_N];           // d row scale
static __device__ float g_diag[B_N];         // diag in log2 units
static __device__ float g_rowsum[B_N];
static __device__ float g_colpart[NT * B_N]; // [rowTile][col]
static __device__ float g_blockRow[64];
static __device__ float g_blockCol[64];

// ---------------- PTX helpers (plain sm_103-safe) --------------------------
__device__ __forceinline__ uint32_t smem_u32(const void* p) {
    uint32_t a;
    asm("{ .reg .u64 t; cvta.to.shared.u64 t, %1; cvt.u32.u64 %0, t; }" : "=r"(a) : "l"(p));
    return a;
}
__device__ __forceinline__ void cp16(uint32_t dst, const void* src) {
    asm volatile("cp.async.cg.shared.global [%0], [%1], 16;" :: "r"(dst), "l"(src) : "memory");
}
#define CP_COMMIT() asm volatile("cp.async.commit_group;" ::: "memory")
#define CP_WAIT(n)  asm volatile("cp.async.wait_group %0;" :: "n"(n) : "memory")

__device__ __forceinline__ float ex2(float x) {
    float r; asm("ex2.approx.ftz.f32 %0, %1;" : "=f"(r) : "f"(x)); return r;
}

#define LDSM4(r0, r1, r2, r3, addr)                                          \
    asm volatile("ldmatrix.sync.aligned.m8n8.x4.shared.b16 {%0,%1,%2,%3}, [%4];" \
        : "=r"(r0), "=r"(r1), "=r"(r2), "=r"(r3) : "r"(addr))

#define IMMA16832(c, a, b)                                                   \
    asm volatile("mma.sync.aligned.m16n8k32.row.col.s32.s8.s8.s32 "          \
        "{%0,%1,%2,%3}, {%4,%5,%6,%7}, {%8,%9}, {%0,%1,%2,%3};"              \
        : "+r"((c)[0]), "+r"((c)[1]), "+r"((c)[2]), "+r"((c)[3])             \
        : "r"((a)[0]), "r"((a)[1]), "r"((a)[2]), "r"((a)[3]),                \
          "r"((b)[0]), "r"((b)[1]))

// ---------------------------------------------------------------------------
// 1. Normalize + int8 quantize. One warp per row; thread owns 8 consecutive.
//    int8 = rint(v * 127 / amax);  scale = amax / (127 * ||v||) [* log2e/T]
// ---------------------------------------------------------------------------
__global__ void normalize_kernel(const float* __restrict__ in, int is_q) {
    int warp = threadIdx.x >> 5;
    int lane = threadIdx.x & 31;
    int row  = blockIdx.x * 8 + warp;
    const float* src = in + (size_t)row * D_K + lane * 8;
    float v[8];
    float ss = 0.f, am = 0.f;
    float4 p0 = *(const float4*)src;
    float4 p1 = *(const float4*)(src + 4);
    v[0] = p0.x; v[1] = p0.y; v[2] = p0.z; v[3] = p0.w;
    v[4] = p1.x; v[5] = p1.y; v[6] = p1.z; v[7] = p1.w;
#pragma unroll
    for (int j = 0; j < 8; ++j) { ss += v[j] * v[j]; am = fmaxf(am, fabsf(v[j])); }
#pragma unroll
    for (int o = 16; o > 0; o >>= 1) {
        ss += __shfl_xor_sync(0xffffffffu, ss, o);
        am = fmaxf(am, __shfl_xor_sync(0xffffffffu, am, o));
    }
    float nrm = fmaxf(sqrtf(ss), 1e-12f);
    float r127 = 127.0f / am;
    int i8[8];
#pragma unroll
    for (int j = 0; j < 8; ++j) {
        int t = __float2int_rn(v[j] * r127);
        i8[j] = max(-127, min(127, t));
    }
    uint32_t lo = (i8[0] & 0xFF) | ((i8[1] & 0xFF) << 8) |
                  ((i8[2] & 0xFF) << 16) | ((i8[3] & 0xFF) << 24);
    uint32_t hi = (i8[4] & 0xFF) | ((i8[5] & 0xFF) << 8) |
                  ((i8[6] & 0xFF) << 16) | ((i8[7] & 0xFF) << 24);
    uint8_t* dst8 = (is_q ? g_q8 : g_d8) + (size_t)row * D_K + lane * 8;
    ((uint32_t*)dst8)[0] = lo;
    ((uint32_t*)dst8)[1] = hi;
    if (lane == 0) {
        float sc = am / (127.0f * nrm);
        if (is_q) g_sq[row] = sc * (LOG2E / 0.07f);
        else      g_sd[row] = sc;
    }
}

// ---------------------------------------------------------------------------
// 2. diag[i] = (q8_i . d8_i) * sq[i] * sd[i]  (dp4a; exact int dot)
// ---------------------------------------------------------------------------
__global__ void diag_kernel() {
    int warp = threadIdx.x >> 5;
    int lane = threadIdx.x & 31;
    int row  = blockIdx.x * 8 + warp;
    const int* a = (const int*)(g_q8 + (size_t)row * D_K);
    const int* b = (const int*)(g_d8 + (size_t)row * D_K);
    int s = 0;
    s = __dp4a(a[lane], b[lane], s);
    s = __dp4a(a[lane + 32], b[lane + 32], s);
#pragma unroll
    for (int o = 16; o > 0; o >>= 1) s += __shfl_xor_sync(0xffffffffu, s, o);
    if (lane == 0) g_diag[row] = (float)s * g_sq[row] * g_sd[row];
}

// ---------------------------------------------------------------------------
// 3. Persistent IMMA GEMM + exp2 partials. Grid 128 (row tiles), 512 threads.
//    Warp grid 4x4: warp = 32 rows x 32 cols (mt2 x nt4 m16n8k32 frags).
//    SMEM: A 32K @0, B x3 32K @32K/64K/96K, sd x3 512B, colred 2K, rowred 2K.
//    Tile layout: [row][16B chunk c], 16 chunks/row, swizzle c ^= (row & 7).
// ---------------------------------------------------------------------------
#define SMEM_B0     32768
#define SMEM_SD0    131072
#define SMEM_COLRED 133120
#define SMEM_ROWRED 135168
#define SMEM_SZ     137216

__device__ __forceinline__ void load_btile(uint32_t sb, int stage, int t, int tid) {
    uint32_t dstBase = sb + SMEM_B0 + stage * 32768;
    const uint8_t* src = g_d8 + (size_t)t * 128 * D_K;
#pragma unroll
    for (int it = 0; it < 4; ++it) {
        int e = it * 512 + tid;          // 0..2047
        int r = e >> 4, c = e & 15;      // row, 16B chunk
        cp16(dstBase + r * 256 + ((c ^ (r & 7)) << 4), src + (size_t)r * D_K + c * 16);
    }
    if (tid < 32)
        cp16(sb + SMEM_SD0 + stage * 512 + tid * 16, g_sd + t * 128 + tid * 4);
}

__global__ __launch_bounds__(512, 1) void gemm_lse_kernel() {
    extern __shared__ char smem[];
    uint32_t sb = smem_u32(smem);
    int tid = threadIdx.x;
    int lane = tid & 31;
    int wid  = tid >> 5;
    int wr = wid >> 2;         // warp row (0..3) -> 32 rows each
    int wc = wid & 3;          // warp col (0..3) -> 32 cols each
    int rowBase = blockIdx.x * 128;

    // group 0: A tile + B tile 0 + sd0 ; group 1: B tile 1 + sd1
    {
        const uint8_t* src = g_q8 + (size_t)rowBase * D_K;
#pragma unroll
        for (int it = 0; it < 4; ++it) {
            int e = it * 512 + tid;
            int r = e >> 4, c = e & 15;
            cp16(sb + r * 256 + ((c ^ (r & 7)) << 4), src + (size_t)r * D_K + c * 16);
        }
    }
    load_btile(sb, 0, 0, tid);
    CP_COMMIT();
    load_btile(sb, 1, 1, tid);
    CP_COMMIT();

    // row scales for this thread's 4 rows (fixed across all tiles)
    float sqr[2][2];
#pragma unroll
    for (int mt = 0; mt < 2; ++mt) {
        int r = rowBase + wr * 32 + mt * 16 + (lane >> 2);
        sqr[mt][0] = g_sq[r];
        sqr[mt][1] = g_sq[r + 8];
    }

    // per-lane ldmatrix row/chunk components
    int aRowL   = wr * 32 + (lane & 15);                          // + mt*16
    int aChunkL = lane >> 4;                                      // + 2*ks
    int bRowL   = wc * 32 + ((lane >> 4) & 1) * 8 + (lane & 7);   // + p*16
    int bChunkL = (lane >> 3) & 1;                                // + 2*ks

    float rp0[2], rp1[2];
    rp0[0] = rp0[1] = rp1[0] = rp1[1] = 0.f;

    float* colred = (float*)(smem + SMEM_COLRED);   // [128][4]

#pragma unroll 1
    for (int t = 0; t < NT; ++t) {
        if (t + 2 < NT) load_btile(sb, (t + 2) % 3, t + 2, tid);
        CP_COMMIT();             // empty groups at the tail keep count uniform
        CP_WAIT(2);              // tile t's group complete
        __syncthreads();

        int acc[2][4][4];
#pragma unroll
        for (int mt = 0; mt < 2; ++mt)
#pragma unroll
            for (int nt = 0; nt < 4; ++nt)
#pragma unroll
                for (int k = 0; k < 4; ++k) acc[mt][nt][k] = 0;

        uint32_t bBase = sb + SMEM_B0 + (t % 3) * 32768;
#pragma unroll
        for (int ks = 0; ks < 8; ++ks) {
            uint32_t a[2][4];
#pragma unroll
            for (int mt = 0; mt < 2; ++mt) {
                int rrow = aRowL + mt * 16;
                int cc = 2 * ks + aChunkL;
                uint32_t ad = sb + rrow * 256 + ((cc ^ (rrow & 7)) << 4);
                LDSM4(a[mt][0], a[mt][1], a[mt][2], a[mt][3], ad);
            }
            uint32_t b[4][2];
#pragma unroll
            for (int p = 0; p < 2; ++p) {
                int rrow = bRowL + p * 16;
                int cc = 2 * ks + bChunkL;
                uint32_t bd = bBase + rrow * 256 + ((cc ^ (rrow & 7)) << 4);
                uint32_t r0, r1, r2, r3;
                LDSM4(r0, r1, r2, r3, bd);
                b[2 * p][0] = r0; b[2 * p][1] = r1;
                b[2 * p + 1][0] = r2; b[2 * p + 1][1] = r3;
            }
#pragma unroll
            for (int mt = 0; mt < 2; ++mt)
#pragma unroll
                for (int nt = 0; nt < 4; ++nt) IMMA16832(acc[mt][nt], a[mt], b[nt]);
        }

        // ---- epilogue: dequant + ex2; rows -> registers, cols -> smem ----
        const float* sdp = (const float*)(smem + SMEM_SD0 + (t % 3) * 512);
        float cq0[4], cq1[4];
#pragma unroll
        for (int i = 0; i < 4; ++i) { cq0[i] = cq1[i] = 0.f; }
#pragma unroll
        for (int nt = 0; nt < 4; ++nt) {
            int c0 = wc * 32 + nt * 8 + (lane & 3) * 2;
            float sd0 = sdp[c0], sd1 = sdp[c0 + 1];
#pragma unroll
            for (int mt = 0; mt < 2; ++mt) {
                float s00 = sqr[mt][0] * sd0, s01 = sqr[mt][0] * sd1;
                float s10 = sqr[mt][1] * sd0, s11 = sqr[mt][1] * sd1;
                float e0 = ex2(fmaf((float)acc[mt][nt][0], s00, -M2_SHIFT));
                float e1 = ex2(fmaf((float)acc[mt][nt][1], s01, -M2_SHIFT));
                float e2 = ex2(fmaf((float)acc[mt][nt][2], s10, -M2_SHIFT));
                float e3 = ex2(fmaf((float)acc[mt][nt][3], s11, -M2_SHIFT));
                rp0[mt] += e0 + e1;
                rp1[mt] += e2 + e3;
                cq0[nt] += e0 + e2;
                cq1[nt] += e1 + e3;
            }
        }
        // col sums: reduce across the 8 lane-groups sharing a col
#pragma unroll
        for (int o = 4; o <= 16; o <<= 1)
#pragma unroll
            for (int nt = 0; nt < 4; ++nt) {
                cq0[nt] += __shfl_xor_sync(0xffffffffu, cq0[nt], o);
                cq1[nt] += __shfl_xor_sync(0xffffffffu, cq1[nt], o);
            }
        if (lane < 4) {
#pragma unroll
            for (int nt = 0; nt < 4; ++nt) {
                int col = wc * 32 + nt * 8 + lane * 2;
                colred[col * 4 + wr]       = cq0[nt];
                colred[(col + 1) * 4 + wr] = cq1[nt];
            }
        }
        __syncthreads();
        if (tid < 128) {
            float cs = colred[tid * 4] + colred[tid * 4 + 1] +
                       colred[tid * 4 + 2] + colred[tid * 4 + 3];
            g_colpart[(size_t)blockIdx.x * B_N + t * 128 + tid] = cs;
        }
    }

    // ---- final row sums (once per CTA) ----
#pragma unroll
    for (int o = 1; o <= 2; o <<= 1)
#pragma unroll
        for (int mt = 0; mt < 2; ++mt) {
            rp0[mt] += __shfl_xor_sync(0xffffffffu, rp0[mt], o);
            rp1[mt] += __shfl_xor_sync(0xffffffffu, rp1[mt], o);
        }
    float* rowred = (float*)(smem + SMEM_ROWRED);   // [128][4]
    __syncthreads();
    if ((lane & 3) == 0) {
        int rloc = wr * 32 + (lane >> 2);
#pragma unroll
        for (int mt = 0; mt < 2; ++mt) {
            rowred[(rloc + mt * 16) * 4 + wc]     = rp0[mt];
            rowred[(rloc + mt * 16 + 8) * 4 + wc] = rp1[mt];
        }
    }
    __syncthreads();
    if (tid < 128) {
        float rs = rowred[tid * 4] + rowred[tid * 4 + 1] +
                   rowred[tid * 4 + 2] + rowred[tid * 4 + 3];
        g_rowsum[rowBase + tid] = rs;
    }
}

// ---------------------------------------------------------------------------
// 4a. Per-row loss terms (log2 domain -> nats) + deterministic tree reduce
// ---------------------------------------------------------------------------
__global__ void finalize1_kernel() {
    int i = blockIdx.x * 256 + threadIdx.x;
    float cs = 0.f;
#pragma unroll 4
    for (int t = 0; t < NT; ++t) cs += g_colpart[(size_t)t * B_N + i];
    float rs = g_rowsum[i];
    float dg = g_diag[i];
    float rw = LN2 * (M2_SHIFT + log2f(rs) - dg);
    float cw = LN2 * (M2_SHIFT + log2f(cs) - dg);

    __shared__ float sr[256], sc[256];
    sr[threadIdx.x] = rw;
    sc[threadIdx.x] = cw;
    __syncthreads();
    for (int o = 128; o > 0; o >>= 1) {
        if (threadIdx.x < o) {
            sr[threadIdx.x] += sr[threadIdx.x + o];
            sc[threadIdx.x] += sc[threadIdx.x + o];
        }
        __syncthreads();
    }
    if (threadIdx.x == 0) {
        g_blockRow[blockIdx.x] = sr[0];
        g_blockCol[blockIdx.x] = sc[0];
    }
}

// 4b. Final scalar
__global__ void finalize2_kernel(float* out) {
    float sR = 0.f, sC = 0.f;
    for (int b = 0; b < 64; ++b) { sR += g_blockRow[b]; sC += g_blockCol[b]; }
    out[0] = (sR + sC) / (2.0f * (float)B_N);
}

// ---------------------------------------------------------------------------
extern "C" void kernel_launch(void* const* d_in, const int* in_sizes, int n_in,
                              void* d_out, int out_size) {
    const float* q = (const float*)d_in[0];
    const float* d = (const float*)d_in[1];
    float* out = (float*)d_out;

    cudaFuncSetAttribute(gemm_lse_kernel,
                         cudaFuncAttributeMaxDynamicSharedMemorySize, SMEM_SZ);

    normalize_kernel<<<B_N / 8, 256>>>(q, 1);
    normalize_kernel<<<B_N / 8, 256>>>(d, 0);
    diag_kernel<<<B_N / 8, 256>>>();
    gemm_lse_kernel<<<NT, 512, SMEM_SZ>>>();
    finalize1_kernel<<<B_N / 256, 256>>>();
    finalize2_kernel<<<1, 1>>>(out);
}

// round 15
// speedup vs baseline: 2.4665x; 2.4665x over previous
#include <cuda_runtime.h>
#include <cuda_bf16.h>
#include <math.h>
#include <cstdint>

// InfoNCE loss. B=16384, D=256, T=0.07. bf16 mma.sync HMMA path
// (compute_103-safe; tcgen05 rejected by toolchain, int8 IMMA measured 8x
// slower per-instr on sm_103a). Persistent row-tile CTAs (128), 256 threads,
// 8 warps (64x32 each). Per-warp tile split into two 16-col halves with the
// stream ordered MMA_h0(t), epi_h1(t-1), MMA_h1(t), epi_h0(t) so the ex2/add
// epilogue interleaves into the HMMA shadow. Per-warp col partials written
// directly to global (no smem col reduce, 1 sync per tile).
// q pre-scaled by log2e/T; fixed shift M2 = log2e/T >= any scaled logit ->
// stable LSE, no atomics, deterministic. sim (1 GB) never materialized.

#define B_N 16384
#define D_K 256
#define NT  128
#define LOG2E 1.4426950408889634f
#define LN2   0.6931471805599453f
#define M2_SHIFT (14.285714285714286f * LOG2E)   // (1/T) * log2(e)

static __device__ __nv_bfloat16 g_qb[B_N * D_K];   // q-hat * log2e/T
static __device__ __nv_bfloat16 g_db[B_N * D_K];   // d-hat
static __device__ float g_diag[B_N];               // diag in log2 units
static __device__ float g_rowsum[B_N];
static __device__ float g_colpart2[NT * 2 * B_N];  // [rowTile][wr][col]
static __device__ float g_blockRow[64];
static __device__ float g_blockCol[64];

// ---------------- PTX helpers (plain sm_103-safe) --------------------------
__device__ __forceinline__ uint32_t smem_u32(const void* p) {
    uint32_t a;
    asm("{ .reg .u64 t; cvta.to.shared.u64 t, %1; cvt.u32.u64 %0, t; }" : "=r"(a) : "l"(p));
    return a;
}
__device__ __forceinline__ void cp16(uint32_t dst, const void* src) {
    asm volatile("cp.async.cg.shared.global [%0], [%1], 16;" :: "r"(dst), "l"(src) : "memory");
}
#define CP_COMMIT() asm volatile("cp.async.commit_group;" ::: "memory")
#define CP_WAIT(n)  asm volatile("cp.async.wait_group %0;" :: "n"(n) : "memory")

__device__ __forceinline__ float ex2(float x) {
    float r; asm("ex2.approx.ftz.f32 %0, %1;" : "=f"(r) : "f"(x)); return r;
}

#define LDSM4(r0, r1, r2, r3, addr)                                          \
    asm volatile("ldmatrix.sync.aligned.m8n8.x4.shared.b16 {%0,%1,%2,%3}, [%4];" \
        : "=r"(r0), "=r"(r1), "=r"(r2), "=r"(r3) : "r"(addr))

#define MMA16816(c, a, b)                                                    \
    asm volatile("mma.sync.aligned.m16n8k16.row.col.f32.bf16.bf16.f32 "      \
        "{%0,%1,%2,%3}, {%4,%5,%6,%7}, {%8,%9}, {%0,%1,%2,%3};"              \
        : "+f"((c)[0]), "+f"((c)[1]), "+f"((c)[2]), "+f"((c)[3])             \
        : "r"((a)[0]), "r"((a)[1]), "r"((a)[2]), "r"((a)[3]),                \
          "r"((b)[0]), "r"((b)[1]))

// ---------------------------------------------------------------------------
// 1. Normalize -> bf16. q scaled by log2e/T. One warp per row.
// ---------------------------------------------------------------------------
__global__ void normalize_kernel(const float* __restrict__ in, int is_q) {
    int warp = threadIdx.x >> 5;
    int lane = threadIdx.x & 31;
    int row  = blockIdx.x * 8 + warp;
    const float* src = in + (size_t)row * D_K;
    float v[8];
    float s = 0.f;
#pragma unroll
    for (int j = 0; j < 8; ++j) { v[j] = src[j * 32 + lane]; s += v[j] * v[j]; }
#pragma unroll
    for (int o = 16; o > 0; o >>= 1) s += __shfl_xor_sync(0xffffffffu, s, o);
    float extra = is_q ? (LOG2E / 0.07f) : 1.0f;
    float scale = extra / fmaxf(sqrtf(s), 1e-12f);
    __nv_bfloat16* dst = (is_q ? g_qb : g_db) + (size_t)row * D_K;
#pragma unroll
    for (int j = 0; j < 8; ++j) dst[j * 32 + lane] = __float2bfloat16(v[j] * scale);
}

// ---------------------------------------------------------------------------
// 2. diag[i] = qb_i . db_i  (log2-scaled units; matches GEMM inputs)
// ---------------------------------------------------------------------------
__global__ void diag_kernel() {
    int warp = threadIdx.x >> 5;
    int lane = threadIdx.x & 31;
    int row  = blockIdx.x * 8 + warp;
    const __nv_bfloat16* a = g_qb + (size_t)row * D_K;
    const __nv_bfloat16* b = g_db + (size_t)row * D_K;
    float s = 0.f;
#pragma unroll
    for (int j = 0; j < 8; ++j) {
        int c = j * 32 + lane;
        s += __bfloat162float(a[c]) * __bfloat162float(b[c]);
    }
#pragma unroll
    for (int o = 16; o > 0; o >>= 1) s += __shfl_xor_sync(0xffffffffu, s, o);
    if (lane == 0) g_diag[row] = s;
}

// ---------------------------------------------------------------------------
// 3. Persistent GEMM + exp2 partials. Grid 128 (row tiles), 256 threads.
//    Warp grid 2x4: warp = 64 rows x 32 cols; cols split into 2 halves of 16.
//    SMEM: A 64K @0, B buf0 @65536, B buf1 @131072, rowred 2K @196608.
//    Tile layout: [row][16B chunk c], 32 chunks/row, swizzle c ^= (row & 7).
// ---------------------------------------------------------------------------
#define SMEM_B0     65536
#define SMEM_B1     131072
#define SMEM_ROWRED 196608
#define SMEM_SZ     198656

__device__ __forceinline__ void load_tile(uint32_t dstBase,
                                          const __nv_bfloat16* src, int tid) {
#pragma unroll
    for (int it = 0; it < 16; ++it) {
        int e = it * 256 + tid;          // 0..4095
        int r = e >> 5, c = e & 31;      // row, 16B chunk (full K=256)
        cp16(dstBase + r * 512 + ((c ^ (r & 7)) << 4),
             (const char*)(src + (size_t)r * D_K) + c * 16);
    }
}

__global__ __launch_bounds__(256, 1) void gemm_lse_kernel() {
    extern __shared__ char smem[];
    uint32_t sb = smem_u32(smem);
    int tid = threadIdx.x;
    int lane = tid & 31;
    int wid  = tid >> 5;
    int wr = wid >> 2;         // warp row (0..1) -> 64 rows
    int wc = wid & 3;          // warp col (0..3) -> 32 cols
    int rowBase = blockIdx.x * 128;

    load_tile(sb, g_qb + (size_t)rowBase * D_K, tid);   // A (q rows) once
    CP_COMMIT();
    load_tile(sb + SMEM_B0, g_db, tid);                 // B tile 0
    CP_COMMIT();

    // per-lane ldmatrix row/chunk components
    int aRowL   = wr * 64 + (lane & 15);                          // + mt*16
    int aChunkL = lane >> 4;                                      // + 2*ks
    int bRowL   = wc * 32 + ((lane >> 4) & 1) * 8 + (lane & 7);   // + h*16
    int bChunkL = (lane >> 3) & 1;                                // + 2*ks

    // row partials accumulate across ALL col tiles (registers)
    float rp0[4], rp1[4];
#pragma unroll
    for (int i = 0; i < 4; ++i) { rp0[i] = rp1[i] = 0.f; }

    // two half-tile accumulator sets: [mt][ntl][frag]
    float acc0[4][2][4], acc1[4][2][4];

    float* cp2base = g_colpart2 + (size_t)(blockIdx.x * 2 + wr) * B_N;

#pragma unroll 1
    for (int t = 0; t < NT; ++t) {
        if (t + 1 < NT) {
            load_tile(sb + (((t + 1) & 1) ? SMEM_B1 : SMEM_B0),
                      g_db + (size_t)(t + 1) * 128 * D_K, tid);
            CP_COMMIT();
            CP_WAIT(1);
        } else {
            CP_WAIT(0);
        }
        __syncthreads();
        uint32_t bBase = sb + ((t & 1) ? SMEM_B1 : SMEM_B0);

        // ===== MMA half 0 (cols wc*32 .. +16) =====
#pragma unroll
        for (int mt = 0; mt < 4; ++mt)
#pragma unroll
            for (int ntl = 0; ntl < 2; ++ntl)
#pragma unroll
                for (int k = 0; k < 4; ++k) acc0[mt][ntl][k] = 0.f;
#pragma unroll
        for (int ks = 0; ks < 16; ++ks) {
            uint32_t a[4][4];
#pragma unroll
            for (int mt = 0; mt < 4; ++mt) {
                int rrow = aRowL + mt * 16;
                int cc = 2 * ks + aChunkL;
                LDSM4(a[mt][0], a[mt][1], a[mt][2], a[mt][3],
                      sb + rrow * 512 + ((cc ^ (rrow & 7)) << 4));
            }
            int rrow = bRowL;                  // h = 0
            int cc = 2 * ks + bChunkL;
            uint32_t b0[2][2];
            {
                uint32_t r0, r1, r2, r3;
                LDSM4(r0, r1, r2, r3, bBase + rrow * 512 + ((cc ^ (rrow & 7)) << 4));
                b0[0][0] = r0; b0[0][1] = r1; b0[1][0] = r2; b0[1][1] = r3;
            }
#pragma unroll
            for (int mt = 0; mt < 4; ++mt)
#pragma unroll
                for (int ntl = 0; ntl < 2; ++ntl) MMA16816(acc0[mt][ntl], a[mt], b0[ntl]);
        }

        // ===== epilogue of PREVIOUS tile's half 1 (interleaves with above) =====
        if (t > 0) {
            float cq0[2], cq1[2];
            cq0[0] = cq0[1] = cq1[0] = cq1[1] = 0.f;
#pragma unroll
            for (int mt = 0; mt < 4; ++mt)
#pragma unroll
                for (int ntl = 0; ntl < 2; ++ntl) {
                    float e0 = ex2(acc1[mt][ntl][0] - M2_SHIFT);
                    float e1 = ex2(acc1[mt][ntl][1] - M2_SHIFT);
                    float e2 = ex2(acc1[mt][ntl][2] - M2_SHIFT);
                    float e3 = ex2(acc1[mt][ntl][3] - M2_SHIFT);
                    rp0[mt] += e0 + e1;
                    rp1[mt] += e2 + e3;
                    cq0[ntl] += e0 + e2;
                    cq1[ntl] += e1 + e3;
                }
#pragma unroll
            for (int o = 4; o <= 16; o <<= 1)
#pragma unroll
                for (int ntl = 0; ntl < 2; ++ntl) {
                    cq0[ntl] += __shfl_xor_sync(0xffffffffu, cq0[ntl], o);
                    cq1[ntl] += __shfl_xor_sync(0xffffffffu, cq1[ntl], o);
                }
            if (lane < 4) {
#pragma unroll
                for (int ntl = 0; ntl < 2; ++ntl) {
                    int col = (t - 1) * 128 + wc * 32 + (2 + ntl) * 8 + lane * 2;
                    cp2base[col]     = cq0[ntl];
                    cp2base[col + 1] = cq1[ntl];
                }
            }
        }

        // ===== MMA half 1 (cols wc*32+16 .. +32) =====
#pragma unroll
        for (int mt = 0; mt < 4; ++mt)
#pragma unroll
            for (int ntl = 0; ntl < 2; ++ntl)
#pragma unroll
                for (int k = 0; k < 4; ++k) acc1[mt][ntl][k] = 0.f;
#pragma unroll
        for (int ks = 0; ks < 16; ++ks) {
            uint32_t a[4][4];
#pragma unroll
            for (int mt = 0; mt < 4; ++mt) {
                int rrow = aRowL + mt * 16;
                int cc = 2 * ks + aChunkL;
                LDSM4(a[mt][0], a[mt][1], a[mt][2], a[mt][3],
                      sb + rrow * 512 + ((cc ^ (rrow & 7)) << 4));
            }
            int rrow = bRowL + 16;             // h = 1
            int cc = 2 * ks + bChunkL;
            uint32_t b1[2][2];
            {
                uint32_t r0, r1, r2, r3;
                LDSM4(r0, r1, r2, r3, bBase + rrow * 512 + ((cc ^ (rrow & 7)) << 4));
                b1[0][0] = r0; b1[0][1] = r1; b1[1][0] = r2; b1[1][1] = r3;
            }
#pragma unroll
            for (int mt = 0; mt < 4; ++mt)
#pragma unroll
                for (int ntl = 0; ntl < 2; ++ntl) MMA16816(acc1[mt][ntl], a[mt], b1[ntl]);
        }

        // ===== epilogue of THIS tile's half 0 (interleaves with above) =====
        {
            float cq0[2], cq1[2];
            cq0[0] = cq0[1] = cq1[0] = cq1[1] = 0.f;
#pragma unroll
            for (int mt = 0; mt < 4; ++mt)
#pragma unroll
                for (int ntl = 0; ntl < 2; ++ntl) {
                    float e0 = ex2(acc0[mt][ntl][0] - M2_SHIFT);
                    float e1 = ex2(acc0[mt][ntl][1] - M2_SHIFT);
                    float e2 = ex2(acc0[mt][ntl][2] - M2_SHIFT);
                    float e3 = ex2(acc0[mt][ntl][3] - M2_SHIFT);
                    rp0[mt] += e0 + e1;
                    rp1[mt] += e2 + e3;
                    cq0[ntl] += e0 + e2;
                    cq1[ntl] += e1 + e3;
                }
#pragma unroll
            for (int o = 4; o <= 16; o <<= 1)
#pragma unroll
                for (int ntl = 0; ntl < 2; ++ntl) {
                    cq0[ntl] += __shfl_xor_sync(0xffffffffu, cq0[ntl], o);
                    cq1[ntl] += __shfl_xor_sync(0xffffffffu, cq1[ntl], o);
                }
            if (lane < 4) {
#pragma unroll
                for (int ntl = 0; ntl < 2; ++ntl) {
                    int col = t * 128 + wc * 32 + ntl * 8 + lane * 2;
                    cp2base[col]     = cq0[ntl];
                    cp2base[col + 1] = cq1[ntl];
                }
            }
        }
    }

    // ===== tail: epilogue of last tile's half 1 =====
    {
        float cq0[2], cq1[2];
        cq0[0] = cq0[1] = cq1[0] = cq1[1] = 0.f;
#pragma unroll
        for (int mt = 0; mt < 4; ++mt)
#pragma unroll
            for (int ntl = 0; ntl < 2; ++ntl) {
                float e0 = ex2(acc1[mt][ntl][0] - M2_SHIFT);
                float e1 = ex2(acc1[mt][ntl][1] - M2_SHIFT);
                float e2 = ex2(acc1[mt][ntl][2] - M2_SHIFT);
                float e3 = ex2(acc1[mt][ntl][3] - M2_SHIFT);
                rp0[mt] += e0 + e1;
                rp1[mt] += e2 + e3;
                cq0[ntl] += e0 + e2;
                cq1[ntl] += e1 + e3;
            }
#pragma unroll
        for (int o = 4; o <= 16; o <<= 1)
#pragma unroll
            for (int ntl = 0; ntl < 2; ++ntl) {
                cq0[ntl] += __shfl_xor_sync(0xffffffffu, cq0[ntl], o);
                cq1[ntl] += __shfl_xor_sync(0xffffffffu, cq1[ntl], o);
            }
        if (lane < 4) {
#pragma unroll
            for (int ntl = 0; ntl < 2; ++ntl) {
                int col = (NT - 1) * 128 + wc * 32 + (2 + ntl) * 8 + lane * 2;
                cp2base[col]     = cq0[ntl];
                cp2base[col + 1] = cq1[ntl];
            }
        }
    }

    // ---- final row sums (once per CTA) ----
#pragma unroll
    for (int o = 1; o <= 2; o <<= 1)
#pragma unroll
        for (int mt = 0; mt < 4; ++mt) {
            rp0[mt] += __shfl_xor_sync(0xffffffffu, rp0[mt], o);
            rp1[mt] += __shfl_xor_sync(0xffffffffu, rp1[mt], o);
        }
    float* rowred = (float*)(smem + SMEM_ROWRED);   // [128][4]
    __syncthreads();
    if ((lane & 3) == 0) {
        int rloc = wr * 64 + (lane >> 2);
#pragma unroll
        for (int mt = 0; mt < 4; ++mt) {
            rowred[(rloc + mt * 16) * 4 + wc]     = rp0[mt];
            rowred[(rloc + mt * 16 + 8) * 4 + wc] = rp1[mt];
        }
    }
    __syncthreads();
    if (tid < 128) {
        float rs = rowred[tid * 4] + rowred[tid * 4 + 1] +
                   rowred[tid * 4 + 2] + rowred[tid * 4 + 3];
        g_rowsum[rowBase + tid] = rs;
    }
}

// ---------------------------------------------------------------------------
// 4a. Per-row loss terms (log2 domain -> nats) + deterministic tree reduce
// ---------------------------------------------------------------------------
__global__ void finalize1_kernel() {
    int i = blockIdx.x * 256 + threadIdx.x;
    float cs = 0.f;
#pragma unroll 4
    for (int t = 0; t < 2 * NT; ++t) cs += g_colpart2[(size_t)t * B_N + i];
    float rs = g_rowsum[i];
    float dg = g_diag[i];
    float rw = LN2 * (M2_SHIFT + log2f(rs) - dg);
    float cw = LN2 * (M2_SHIFT + log2f(cs) - dg);

    __shared__ float sr[256], sc[256];
    sr[threadIdx.x] = rw;
    sc[threadIdx.x] = cw;
    __syncthreads();
    for (int o = 128; o > 0; o >>= 1) {
        if (threadIdx.x < o) {
            sr[threadIdx.x] += sr[threadIdx.x + o];
            sc[threadIdx.x] += sc[threadIdx.x + o];
        }
        __syncthreads();
    }
    if (threadIdx.x == 0) {
        g_blockRow[blockIdx.x] = sr[0];
        g_blockCol[blockIdx.x] = sc[0];
    }
}

// 4b. Final scalar
__global__ void finalize2_kernel(float* out) {
    float sR = 0.f, sC = 0.f;
    for (int b = 0; b < 64; ++b) { sR += g_blockRow[b]; sC += g_blockCol[b]; }
    out[0] = (sR + sC) / (2.0f * (float)B_N);
}

// ---------------------------------------------------------------------------
extern "C" void kernel_launch(void* const* d_in, const int* in_sizes, int n_in,
                              void* d_out, int out_size) {
    const float* q = (const float*)d_in[0];
    const float* d = (const float*)d_in[1];
    float* out = (float*)d_out;

    cudaFuncSetAttribute(gemm_lse_kernel,
                         cudaFuncAttributeMaxDynamicSharedMemorySize, SMEM_SZ);

    normalize_kernel<<<B_N / 8, 256>>>(q, 1);
    normalize_kernel<<<B_N / 8, 256>>>(d, 0);
    diag_kernel<<<B_N / 8, 256>>>();
    gemm_lse_kernel<<<NT, 256, SMEM_SZ>>>();
    finalize1_kernel<<<B_N / 256, 256>>>();
    finalize2_kernel<<<1, 1>>>(out);
}

// round 16
// speedup vs baseline: 2.9360x; 1.1903x over previous
#include <cuda_runtime.h>
#include <cuda_bf16.h>
#include <math.h>
#include <cstdint>

// InfoNCE loss. B=16384, D=256, T=0.07. bf16 mma.sync HMMA (compute_103-safe).
// Persistent row-tile CTAs (128), 256 threads / 8 warps (64x32 each).
// B split into 4 per-pair 32-col slices, each double-buffered and synced with
// a 64-thread named barrier -> NO CTA-wide barrier in the mainloop, so warp
// pairs drift and LDSM/MUFU of one pair overlaps HMMA of the other on each
// SMSP (pair mapping wr=wid&1, wc=wid>>1 puts same-SMSP warps in different
// pairs). q pre-scaled by log2e/T; fixed shift M2 >= any logit -> stable LSE,
// no atomics, deterministic. sim (1 GB) never materialized.

#define B_N 16384
#define D_K 256
#define NT  128
#define LOG2E 1.4426950408889634f
#define LN2   0.6931471805599453f
#define M2_SHIFT (14.285714285714286f * LOG2E)   // (1/T) * log2(e)

static __device__ __nv_bfloat16 g_qb[B_N * D_K];   // q-hat * log2e/T
static __device__ __nv_bfloat16 g_db[B_N * D_K];   // d-hat
static __device__ float g_diag[B_N];               // diag in log2 units
static __device__ float g_rowsum[B_N];
static __device__ float g_colpart2[NT * 2 * B_N];  // [rowTile][wr][col]
static __device__ float g_blockRow[64];
static __device__ float g_blockCol[64];

// ---------------- PTX helpers (plain sm_103-safe) --------------------------
__device__ __forceinline__ uint32_t smem_u32(const void* p) {
    uint32_t a;
    asm("{ .reg .u64 t; cvta.to.shared.u64 t, %1; cvt.u32.u64 %0, t; }" : "=r"(a) : "l"(p));
    return a;
}
__device__ __forceinline__ void cp16(uint32_t dst, const void* src) {
    asm volatile("cp.async.cg.shared.global [%0], [%1], 16;" :: "r"(dst), "l"(src) : "memory");
}
#define CP_COMMIT() asm volatile("cp.async.commit_group;" ::: "memory")
#define CP_WAIT(n)  asm volatile("cp.async.wait_group %0;" :: "n"(n) : "memory")
#define BARP(id)    asm volatile("bar.sync %0, 64;" :: "r"(id) : "memory")

__device__ __forceinline__ float ex2(float x) {
    float r; asm("ex2.approx.ftz.f32 %0, %1;" : "=f"(r) : "f"(x)); return r;
}

#define LDSM4(r0, r1, r2, r3, addr)                                          \
    asm volatile("ldmatrix.sync.aligned.m8n8.x4.shared.b16 {%0,%1,%2,%3}, [%4];" \
        : "=r"(r0), "=r"(r1), "=r"(r2), "=r"(r3) : "r"(addr))

#define MMA16816(c, a, b)                                                    \
    asm volatile("mma.sync.aligned.m16n8k16.row.col.f32.bf16.bf16.f32 "      \
        "{%0,%1,%2,%3}, {%4,%5,%6,%7}, {%8,%9}, {%0,%1,%2,%3};"              \
        : "+f"((c)[0]), "+f"((c)[1]), "+f"((c)[2]), "+f"((c)[3])             \
        : "r"((a)[0]), "r"((a)[1]), "r"((a)[2]), "r"((a)[3]),                \
          "r"((b)[0]), "r"((b)[1]))

// ---------------------------------------------------------------------------
// 1. Normalize -> bf16. q scaled by log2e/T. One warp per row.
// ---------------------------------------------------------------------------
__global__ void normalize_kernel(const float* __restrict__ in, int is_q) {
    int warp = threadIdx.x >> 5;
    int lane = threadIdx.x & 31;
    int row  = blockIdx.x * 8 + warp;
    const float* src = in + (size_t)row * D_K;
    float v[8];
    float s = 0.f;
#pragma unroll
    for (int j = 0; j < 8; ++j) { v[j] = src[j * 32 + lane]; s += v[j] * v[j]; }
#pragma unroll
    for (int o = 16; o > 0; o >>= 1) s += __shfl_xor_sync(0xffffffffu, s, o);
    float extra = is_q ? (LOG2E / 0.07f) : 1.0f;
    float scale = extra / fmaxf(sqrtf(s), 1e-12f);
    __nv_bfloat16* dst = (is_q ? g_qb : g_db) + (size_t)row * D_K;
#pragma unroll
    for (int j = 0; j < 8; ++j) dst[j * 32 + lane] = __float2bfloat16(v[j] * scale);
}

// ---------------------------------------------------------------------------
// 2. diag[i] = qb_i . db_i  (log2-scaled units; matches GEMM inputs)
// ---------------------------------------------------------------------------
__global__ void diag_kernel() {
    int warp = threadIdx.x >> 5;
    int lane = threadIdx.x & 31;
    int row  = blockIdx.x * 8 + warp;
    const __nv_bfloat16* a = g_qb + (size_t)row * D_K;
    const __nv_bfloat16* b = g_db + (size_t)row * D_K;
    float s = 0.f;
#pragma unroll
    for (int j = 0; j < 8; ++j) {
        int c = j * 32 + lane;
        s += __bfloat162float(a[c]) * __bfloat162float(b[c]);
    }
#pragma unroll
    for (int o = 16; o > 0; o >>= 1) s += __shfl_xor_sync(0xffffffffu, s, o);
    if (lane == 0) g_diag[row] = s;
}

// ---------------------------------------------------------------------------
// 3. Persistent GEMM + exp2 partials. Grid 128 (row tiles), 256 threads.
//    Warp (wr=wid&1, wc=wid>>1): 64 rows x 32 cols. Pair wc = warps {2wc,2wc+1}
//    owns B slice cols wc*32..+32, double-buffered (16 KB/stage).
//    SMEM: A 64K @0; B slices 4 x 2 x 16K @65536; rowred 2K @196608.
//    Layout: [row][16B chunk c], 32 chunks/row (512B), swizzle c ^= (row&7).
// ---------------------------------------------------------------------------
#define SMEM_B      65536
#define SMEM_ROWRED 196608
#define SMEM_SZ     198656

__global__ __launch_bounds__(256, 1) void gemm_lse_kernel() {
    extern __shared__ char smem[];
    uint32_t sb = smem_u32(smem);
    int tid = threadIdx.x;
    int lane = tid & 31;
    int wid  = tid >> 5;
    int wr = wid & 1;          // row half (0..1) -> 64 rows
    int wc = wid >> 1;         // pair / col group (0..3) -> 32 cols
    int rowBase = blockIdx.x * 128;
    int wtid = wr * 32 + lane;               // 0..63 within pair
    uint32_t sliceBase = sb + SMEM_B + wc * 32768;

    // ---- A tile (once): 256 threads stripe 128 rows x 32 chunks ----
    {
        const __nv_bfloat16* src = g_qb + (size_t)rowBase * D_K;
#pragma unroll
        for (int it = 0; it < 16; ++it) {
            int e = it * 256 + tid;
            int r = e >> 5, c = e & 31;
            cp16(sb + r * 512 + ((c ^ (r & 7)) << 4),
                 (const char*)(src + (size_t)r * D_K) + c * 16);
        }
        CP_COMMIT();
    }
    // ---- B slice loader: pair's 64 threads stripe 32 rows x 32 chunks ----
    auto load_bslice = [&](int stage, int t) {
        uint32_t dstBase = sliceBase + stage * 16384;
        const __nv_bfloat16* src = g_db + (size_t)(t * 128 + wc * 32) * D_K;
#pragma unroll
        for (int it = 0; it < 16; ++it) {
            int e = it * 64 + wtid;          // 0..1023
            int r = e >> 5, c = e & 31;
            cp16(dstBase + r * 512 + ((c ^ (r & 7)) << 4),
                 (const char*)(src + (size_t)r * D_K) + c * 16);
        }
    };
    load_bslice(0, 0);
    CP_COMMIT();
    load_bslice(1, 1);
    CP_COMMIT();
    CP_WAIT(2);                // A landed
    __syncthreads();           // A visible to all warps; only CTA-wide sync

    // per-lane ldmatrix row/chunk components
    int aRowL   = wr * 64 + (lane & 15);                          // + mt*16
    int aChunkL = lane >> 4;                                      // + 2*ks
    int bRowL   = ((lane >> 4) & 1) * 8 + (lane & 7);             // + h*16 (slice-local)
    int bChunkL = (lane >> 3) & 1;                                // + 2*ks
    int barid   = 1 + wc;

    float rp0[4], rp1[4];
#pragma unroll
    for (int i = 0; i < 4; ++i) { rp0[i] = rp1[i] = 0.f; }

    float* cp2base = g_colpart2 + (size_t)(blockIdx.x * 2 + wr) * B_N;

#pragma unroll 1
    for (int t = 0; t < NT; ++t) {
        CP_WAIT(1);            // B(t) landed (B(t+1) may be in flight)
        BARP(barid);           // partner's loads visible too

        float acc[4][4][4];
#pragma unroll
        for (int mt = 0; mt < 4; ++mt)
#pragma unroll
            for (int nt = 0; nt < 4; ++nt)
#pragma unroll
                for (int k = 0; k < 4; ++k) acc[mt][nt][k] = 0.f;

        uint32_t bBase = sliceBase + (t & 1) * 16384;
#pragma unroll
        for (int ks = 0; ks < 16; ++ks) {
            uint32_t a[4][4];
#pragma unroll
            for (int mt = 0; mt < 4; ++mt) {
                int rrow = aRowL + mt * 16;
                int cc = 2 * ks + aChunkL;
                LDSM4(a[mt][0], a[mt][1], a[mt][2], a[mt][3],
                      sb + rrow * 512 + ((cc ^ (rrow & 7)) << 4));
            }
            uint32_t b[4][2];
#pragma unroll
            for (int h = 0; h < 2; ++h) {
                int rrow = bRowL + h * 16;
                int cc = 2 * ks + bChunkL;
                uint32_t r0, r1, r2, r3;
                LDSM4(r0, r1, r2, r3, bBase + rrow * 512 + ((cc ^ (rrow & 7)) << 4));
                b[2 * h][0] = r0; b[2 * h][1] = r1;
                b[2 * h + 1][0] = r2; b[2 * h + 1][1] = r3;
            }
#pragma unroll
            for (int mt = 0; mt < 4; ++mt)
#pragma unroll
                for (int nt = 0; nt < 4; ++nt) MMA16816(acc[mt][nt], a[mt], b[nt]);
        }

        // ---- epilogue: ex2(sim2 - M2); rows -> registers, cols -> global ----
        float cq0[4], cq1[4];
#pragma unroll
        for (int i = 0; i < 4; ++i) { cq0[i] = cq1[i] = 0.f; }
#pragma unroll
        for (int mt = 0; mt < 4; ++mt)
#pragma unroll
            for (int nt = 0; nt < 4; ++nt) {
                float e0 = ex2(acc[mt][nt][0] - M2_SHIFT);
                float e1 = ex2(acc[mt][nt][1] - M2_SHIFT);
                float e2 = ex2(acc[mt][nt][2] - M2_SHIFT);
                float e3 = ex2(acc[mt][nt][3] - M2_SHIFT);
                rp0[mt] += e0 + e1;
                rp1[mt] += e2 + e3;
                cq0[nt] += e0 + e2;
                cq1[nt] += e1 + e3;
            }
#pragma unroll
        for (int o = 4; o <= 16; o <<= 1)
#pragma unroll
            for (int nt = 0; nt < 4; ++nt) {
                cq0[nt] += __shfl_xor_sync(0xffffffffu, cq0[nt], o);
                cq1[nt] += __shfl_xor_sync(0xffffffffu, cq1[nt], o);
            }
        if (lane < 4) {
#pragma unroll
            for (int nt = 0; nt < 4; ++nt) {
                int col = t * 128 + wc * 32 + nt * 8 + lane * 2;
                cp2base[col]     = cq0[nt];
                cp2base[col + 1] = cq1[nt];
            }
        }

        BARP(barid);           // partner done reading buf(t&1): safe to overwrite
        if (t + 2 < NT) load_bslice(t & 1, t + 2);
        CP_COMMIT();           // empty groups at the tail keep count uniform
    }

    // ---- final row sums (once per CTA) ----
#pragma unroll
    for (int o = 1; o <= 2; o <<= 1)
#pragma unroll
        for (int mt = 0; mt < 4; ++mt) {
            rp0[mt] += __shfl_xor_sync(0xffffffffu, rp0[mt], o);
            rp1[mt] += __shfl_xor_sync(0xffffffffu, rp1[mt], o);
        }
    float* rowred = (float*)(smem + SMEM_ROWRED);   // [128][4]
    __syncthreads();
    if ((lane & 3) == 0) {
        int rloc = wr * 64 + (lane >> 2);
#pragma unroll
        for (int mt = 0; mt < 4; ++mt) {
            rowred[(rloc + mt * 16) * 4 + wc]     = rp0[mt];
            rowred[(rloc + mt * 16 + 8) * 4 + wc] = rp1[mt];
        }
    }
    __syncthreads();
    if (tid < 128) {
        float rs = rowred[tid * 4] + rowred[tid * 4 + 1] +
                   rowred[tid * 4 + 2] + rowred[tid * 4 + 3];
        g_rowsum[rowBase + tid] = rs;
    }
}

// ---------------------------------------------------------------------------
// 4a. Per-row loss terms (log2 domain -> nats) + deterministic tree reduce
// ---------------------------------------------------------------------------
__global__ void finalize1_kernel() {
    int i = blockIdx.x * 256 + threadIdx.x;
    float cs = 0.f;
#pragma unroll 4
    for (int t = 0; t < 2 * NT; ++t) cs += g_colpart2[(size_t)t * B_N + i];
    float rs = g_rowsum[i];
    float dg = g_diag[i];
    float rw = LN2 * (M2_SHIFT + log2f(rs) - dg);
    float cw = LN2 * (M2_SHIFT + log2f(cs) - dg);

    __shared__ float sr[256], sc[256];
    sr[threadIdx.x] = rw;
    sc[threadIdx.x] = cw;
    __syncthreads();
    for (int o = 128; o > 0; o >>= 1) {
        if (threadIdx.x < o) {
            sr[threadIdx.x] += sr[threadIdx.x + o];
            sc[threadIdx.x] += sc[threadIdx.x + o];
        }
        __syncthreads();
    }
    if (threadIdx.x == 0) {
        g_blockRow[blockIdx.x] = sr[0];
        g_blockCol[blockIdx.x] = sc[0];
    }
}

// 4b. Final scalar
__global__ void finalize2_kernel(float* out) {
    float sR = 0.f, sC = 0.f;
    for (int b = 0; b < 64; ++b) { sR += g_blockRow[b]; sC += g_blockCol[b]; }
    out[0] = (sR + sC) / (2.0f * (float)B_N);
}

// ---------------------------------------------------------------------------
extern "C" void kernel_launch(void* const* d_in, const int* in_sizes, int n_in,
                              void* d_out, int out_size) {
    const float* q = (const float*)d_in[0];
    const float* d = (const float*)d_in[1];
    float* out = (float*)d_out;

    cudaFuncSetAttribute(gemm_lse_kernel,
                         cudaFuncAttributeMaxDynamicSharedMemorySize, SMEM_SZ);

    normalize_kernel<<<B_N / 8, 256>>>(q, 1);
    normalize_kernel<<<B_N / 8, 256>>>(d, 0);
    diag_kernel<<<B_N / 8, 256>>>();
    gemm_lse_kernel<<<NT, 256, SMEM_SZ>>>();
    finalize1_kernel<<<B_N / 256, 256>>>();
    finalize2_kernel<<<1, 1>>>(out);
}